// round 14
// baseline (speedup 1.0000x reference)
#include <cuda_runtime.h>
#include <cuda_fp16.h>
#include <cstdint>
#include <cstddef>

#define NMAX 100000
#define EMAX 1600000
#define D 128
#define SLOT 64

// ---------------- static device scratch ----------------
__device__ __half g_H[(size_t)NMAX * D];    // ping buffer, fp16 (pre-scaled G)
__device__ __half g_A[(size_t)NMAX * D];    // pong buffer, fp16
__device__ int    g_cnt[NMAX];              // in-degree (k_count)
__device__ int    g_cur[NMAX];              // scatter cursor
__device__ float  g_dis[NMAX];
__device__ int    g_csrs[(size_t)NMAX * SLOT];  // fixed-slot CSR (25.6 MB)
__device__ float  g_Wt[128 * 128];          // W0*W1
__device__ float  g_W012[128 * 128];        // W0*W1*W2
__device__ float  g_c1[128];                // b0*W1*W2
__device__ float  g_c2[128];                // b1*W2
__device__ float  g_u1[NMAX];               // A*1
__device__ float  g_t1[NMAX];               // dis * u1
__device__ float  g_u2[NMAX];               // A^2*1

// ---------------- graph preprocessing ----------------
__global__ void k_zero(int n) {
    int i = blockIdx.x * blockDim.x + threadIdx.x;
    if (i < n) { g_cnt[i] = 0; g_cur[i] = 0; }
}

__global__ void k_count(const int* __restrict__ dst, int e) {
    int i = blockIdx.x * blockDim.x + threadIdx.x;
    if (i < e) atomicAdd(&g_cnt[dst[i]], 1);
}

__global__ void k_dis(int n) {
    int i = blockIdx.x * blockDim.x + threadIdx.x;
    if (i < n) g_dis[i] = rsqrtf((float)(g_cnt[i] + 1));   // +1 self loop
}

// fixed-slot scatter: no scan needed
__global__ void k_scatter(const int* __restrict__ src, const int* __restrict__ dst, int e) {
    int i = blockIdx.x * blockDim.x + threadIdx.x;
    if (i < e) {
        int d = dst[i];
        int p = atomicAdd(&g_cur[d], 1);
        if (p < SLOT) g_csrs[(size_t)d * SLOT + p] = src[i];
    }
}

// ---------------- tiny fp32 matmul: C[128x128] = A*B ----------------
__global__ void k_mm128(const float* __restrict__ A, const float* __restrict__ B,
                        float* __restrict__ C) {
    int id = blockIdx.x * 256 + threadIdx.x;
    int r = id >> 7, c = id & 127;
    float s = 0.0f;
#pragma unroll 8
    for (int k = 0; k < 128; k++) s = fmaf(A[r * 128 + k], B[k * 128 + c], s);
    C[id] = s;
}

// ---------------- bias correction vectors: c1 = b0*W1*W2, c2 = b1*W2 ----------------
__global__ void k_cvec(const float* __restrict__ b0, const float* __restrict__ b1,
                       const float* __restrict__ W1, const float* __restrict__ W2) {
    __shared__ float t1[128];
    int j = threadIdx.x;
    float s = 0.0f;
    for (int k = 0; k < 128; k++) s = fmaf(b0[k], W1[k * 128 + j], s);
    t1[j] = s;
    __syncthreads();
    float s1 = 0.0f, s2 = 0.0f;
    for (int k = 0; k < 128; k++) {
        float w = W2[k * 128 + j];
        s1 = fmaf(t1[k], w, s1);
        s2 = fmaf(b1[k], w, s2);
    }
    g_c1[j] = s1;
    g_c2[j] = s2;
}

// ---------------- scalar aggregations: u1 = A*1, u2 = A*u1 (weight-free form) ----------------
__global__ void k_aggs1(int n) {
    int v = blockIdx.x * blockDim.x + threadIdx.x;
    if (v >= n) return;
    float dv = g_dis[v];
    float s = dv;                               // self: G=dis
    int len = g_cnt[v]; if (len > SLOT) len = SLOT;
    const int* seg = g_csrs + (size_t)v * SLOT;
    for (int e = 0; e < len; e++) s += g_dis[seg[e]];
    float u1 = dv * s;
    g_u1[v] = u1;
    g_t1[v] = dv * u1;
}

__global__ void k_aggs2(int n) {
    int v = blockIdx.x * blockDim.x + threadIdx.x;
    if (v >= n) return;
    float dv = g_dis[v];
    float s = g_t1[v];                          // self: dis*u1
    int len = g_cnt[v]; if (len > SLOT) len = SLOT;
    const int* seg = g_csrs + (size_t)v * SLOT;
    for (int e = 0; e < len; e++) s += g_t1[seg[e]];
    g_u2[v] = dv * s;
}

// ---------------- MMA helpers ----------------
__device__ __forceinline__ void mma_f16(float* c, const unsigned* a, unsigned b0, unsigned b1) {
    asm volatile(
        "mma.sync.aligned.m16n8k16.row.col.f32.f16.f16.f32 "
        "{%0,%1,%2,%3}, {%4,%5,%6,%7}, {%8,%9}, {%0,%1,%2,%3};\n"
        : "+f"(c[0]), "+f"(c[1]), "+f"(c[2]), "+f"(c[3])
        : "r"(a[0]), "r"(a[1]), "r"(a[2]), "r"(a[3]), "r"(b0), "r"(b1));
}

#define BSTR 136   // smem stride in uint32 -> conflict-free frag loads

// ---------------- GEMM: G0 = diag(dis) * (X @ W012), fp16 out ----------------
__global__ void __launch_bounds__(256)
k_gemm(const float* __restrict__ X, const float* __restrict__ W,
       __half* __restrict__ H, int n) {
    __shared__ unsigned Bh[64 * BSTR];

    int tid = threadIdx.x;
    for (int i = tid; i < 64 * 128; i += 256) {
        int j = i >> 7, c = i & 127;
        float w0 = W[(2 * j) * 128 + c];
        float w1 = W[(2 * j + 1) * 128 + c];
        __half2 h = __floats2half2_rn(w0, w1);
        Bh[j * BSTR + c] = *(unsigned*)&h;
    }
    __syncthreads();

    int wid = tid >> 5, lane = tid & 31;
    int warp_m = wid >> 1, warp_n = wid & 1;
    int g = lane >> 2, tg = lane & 3;
    int rbase = blockIdx.x * 128 + warp_m * 32;
    int cbase = warp_n * 64;
    int nclamp = n - 1;

    float acc[2][8][4];
#pragma unroll
    for (int mf = 0; mf < 2; mf++)
#pragma unroll
        for (int nt = 0; nt < 8; nt++)
#pragma unroll
            for (int q = 0; q < 4; q++) acc[mf][nt][q] = 0.0f;

    for (int k0 = 0; k0 < 128; k0 += 16) {
        unsigned a[2][4];
#pragma unroll
        for (int mf = 0; mf < 2; mf++) {
            int r0 = rbase + mf * 16 + g;
            int r1 = r0 + 8;
            if (r0 > nclamp) r0 = nclamp;
            if (r1 > nclamp) r1 = nclamp;
            const float* p0 = X + (size_t)r0 * D + k0 + 2 * tg;
            const float* p1 = X + (size_t)r1 * D + k0 + 2 * tg;
            float2 f00 = *(const float2*)(p0);
            float2 f01 = *(const float2*)(p0 + 8);
            float2 f10 = *(const float2*)(p1);
            float2 f11 = *(const float2*)(p1 + 8);
            __half2 h0 = __floats2half2_rn(f00.x, f00.y);
            __half2 h1 = __floats2half2_rn(f10.x, f10.y);
            __half2 h2 = __floats2half2_rn(f01.x, f01.y);
            __half2 h3 = __floats2half2_rn(f11.x, f11.y);
            a[mf][0] = *(unsigned*)&h0;
            a[mf][1] = *(unsigned*)&h1;
            a[mf][2] = *(unsigned*)&h2;
            a[mf][3] = *(unsigned*)&h3;
        }
#pragma unroll
        for (int nt = 0; nt < 8; nt++) {
            int c = cbase + nt * 8 + g;
            int i0 = (k0 / 2 + tg) * BSTR + c;
            int i1 = i0 + 4 * BSTR;
            unsigned b0 = Bh[i0], b1 = Bh[i1];
#pragma unroll
            for (int mf = 0; mf < 2; mf++)
                mma_f16(acc[mf][nt], a[mf], b0, b1);
        }
    }

#pragma unroll
    for (int mf = 0; mf < 2; mf++) {
        int r0 = rbase + mf * 16 + g;
        int r1 = r0 + 8;
        float d0 = (r0 < n) ? g_dis[r0] : 0.0f;
        float d1 = (r1 < n) ? g_dis[r1] : 0.0f;
#pragma unroll
        for (int nt = 0; nt < 8; nt++) {
            int c = cbase + nt * 8 + 2 * tg;
            if (r0 < n) {
                __half2 v = __floats2half2_rn(d0 * acc[mf][nt][0], d0 * acc[mf][nt][1]);
                *(__half2*)(H + (size_t)r0 * D + c) = v;
            }
            if (r1 < n) {
                __half2 v = __floats2half2_rn(d1 * acc[mf][nt][2], d1 * acc[mf][nt][3]);
                *(__half2*)(H + (size_t)r1 * D + c) = v;
            }
        }
    }
}

// ---------------- aggregation: weight-free sum of pre-scaled rows ----------------
__device__ __forceinline__ void unpack_add8(float* acc, uint4 u) {
    float2 p0 = __half22float2(*(__half2*)&u.x);
    float2 p1 = __half22float2(*(__half2*)&u.y);
    float2 p2 = __half22float2(*(__half2*)&u.z);
    float2 p3 = __half22float2(*(__half2*)&u.w);
    acc[0] += p0.x; acc[1] += p0.y;
    acc[2] += p1.x; acc[3] += p1.y;
    acc[4] += p2.x; acc[5] += p2.y;
    acc[6] += p3.x; acc[7] += p3.y;
}

__device__ __forceinline__ void agg_sum(const uint4* __restrict__ H4, int node,
                                        int half, int c16, float* acc) {
#pragma unroll
    for (int i = 0; i < 8; i++) acc[i] = 0.0f;

    if (half == 0) {
        uint4 uv = H4[(size_t)node * 16 + c16];
        unpack_add8(acc, uv);
    }

    const int* seg = g_csrs + (size_t)node * SLOT;
    int len = g_cnt[node]; if (len > SLOT) len = SLOT;
    int e = 0;
    for (; e + 8 <= len; e += 8) {
        int i0 = e + half, i1 = e + 2 + half, i2 = e + 4 + half, i3 = e + 6 + half;
        int s0 = seg[i0], s1 = seg[i1], s2 = seg[i2], s3 = seg[i3];
        uint4 u0 = H4[(size_t)s0 * 16 + c16];
        uint4 u1 = H4[(size_t)s1 * 16 + c16];
        uint4 u2 = H4[(size_t)s2 * 16 + c16];
        uint4 u3 = H4[(size_t)s3 * 16 + c16];
        unpack_add8(acc, u0);
        unpack_add8(acc, u1);
        unpack_add8(acc, u2);
        unpack_add8(acc, u3);
    }
    for (; e < len; e += 2) {
        int idx = e + half;
        if (idx < len) {
            uint4 u = H4[(size_t)seg[idx] * 16 + c16];
            unpack_add8(acc, u);
        }
    }
#pragma unroll
    for (int i = 0; i < 8; i++)
        acc[i] += __shfl_xor_sync(0xffffffffu, acc[i], 16);
}

// mid aggregation: writes dis^2 * S (pre-scaled for next pass), fp16
__global__ void k_agg_mid(const __half* __restrict__ Hh, __half* __restrict__ Oh, int n) {
    int warp = (blockIdx.x * blockDim.x + threadIdx.x) >> 5;
    int lane = threadIdx.x & 31;
    if (warp >= n) return;
    int half = lane >> 4, c16 = lane & 15;

    float acc[8];
    agg_sum((const uint4*)Hh, warp, half, c16, acc);

    if (half == 0) {
        float dv = g_dis[warp];
        float s2 = dv * dv;
        __half2 h0 = __floats2half2_rn(s2 * acc[0], s2 * acc[1]);
        __half2 h1 = __floats2half2_rn(s2 * acc[2], s2 * acc[3]);
        __half2 h2 = __floats2half2_rn(s2 * acc[4], s2 * acc[5]);
        __half2 h3 = __floats2half2_rn(s2 * acc[6], s2 * acc[7]);
        uint4 o;
        o.x = *(unsigned*)&h0;
        o.y = *(unsigned*)&h1;
        o.z = *(unsigned*)&h2;
        o.w = *(unsigned*)&h3;
        ((uint4*)Oh)[(size_t)warp * 16 + c16] = o;
    }
}

// final aggregation: dis * S + rank-1 bias corrections + b2, fp32 out
__global__ void k_agg_fin(const __half* __restrict__ Hh, const float* __restrict__ b2,
                          float* __restrict__ out, int n) {
    int warp = (blockIdx.x * blockDim.x + threadIdx.x) >> 5;
    int lane = threadIdx.x & 31;
    if (warp >= n) return;
    int half = lane >> 4, c16 = lane & 15;

    float acc[8];
    agg_sum((const uint4*)Hh, warp, half, c16, acc);

    if (half == 0) {
        float dv  = g_dis[warp];
        float u2v = g_u2[warp];
        float u1v = g_u1[warp];
        float4 c1a = ((const float4*)g_c1)[c16 * 2];
        float4 c1b = ((const float4*)g_c1)[c16 * 2 + 1];
        float4 c2a = ((const float4*)g_c2)[c16 * 2];
        float4 c2b = ((const float4*)g_c2)[c16 * 2 + 1];
        float4 ba  = ((const float4*)b2)[c16 * 2];
        float4 bb  = ((const float4*)b2)[c16 * 2 + 1];

        float4 oa, ob;
        oa.x = dv * acc[0] + u2v * c1a.x + u1v * c2a.x + ba.x;
        oa.y = dv * acc[1] + u2v * c1a.y + u1v * c2a.y + ba.y;
        oa.z = dv * acc[2] + u2v * c1a.z + u1v * c2a.z + ba.z;
        oa.w = dv * acc[3] + u2v * c1a.w + u1v * c2a.w + ba.w;
        ob.x = dv * acc[4] + u2v * c1b.x + u1v * c2b.x + bb.x;
        ob.y = dv * acc[5] + u2v * c1b.y + u1v * c2b.y + bb.y;
        ob.z = dv * acc[6] + u2v * c1b.z + u1v * c2b.z + bb.z;
        ob.w = dv * acc[7] + u2v * c1b.w + u1v * c2b.w + bb.w;
        ((float4*)out)[(size_t)warp * 32 + c16 * 2]     = oa;
        ((float4*)out)[(size_t)warp * 32 + c16 * 2 + 1] = ob;
    }
}

// ---------------- launch ----------------
extern "C" void kernel_launch(void* const* d_in, const int* in_sizes, int n_in,
                              void* d_out, int out_size) {
    const float* feat = (const float*)d_in[0];
    const int*   ei   = (const int*)d_in[1];
    const float* W0 = (const float*)d_in[2];
    const float* b0 = (const float*)d_in[3];
    const float* W1 = (const float*)d_in[4];
    const float* b1 = (const float*)d_in[5];
    const float* W2 = (const float*)d_in[6];
    const float* b2 = (const float*)d_in[7];

    int n = in_sizes[0] / D;
    int e = in_sizes[1] / 2;
    if (n > NMAX) n = NMAX;
    if (e > EMAX) e = EMAX;
    const int* src = ei;
    const int* dstp = ei + e;

    __half *Hp, *Ap;
    float *Wtp, *W012p;
    cudaGetSymbolAddress((void**)&Hp, g_H);
    cudaGetSymbolAddress((void**)&Ap, g_A);
    cudaGetSymbolAddress((void**)&Wtp, g_Wt);
    cudaGetSymbolAddress((void**)&W012p, g_W012);

    static cudaStream_t s_side = nullptr;
    static cudaEvent_t  s_fork = nullptr, s_cnt = nullptr, s_disv = nullptr,
                        s_csr = nullptr, s_scal = nullptr;
    if (!s_side) {
        cudaStreamCreateWithFlags(&s_side, cudaStreamNonBlocking);
        cudaEventCreateWithFlags(&s_fork, cudaEventDisableTiming);
        cudaEventCreateWithFlags(&s_cnt, cudaEventDisableTiming);
        cudaEventCreateWithFlags(&s_disv, cudaEventDisableTiming);
        cudaEventCreateWithFlags(&s_csr, cudaEventDisableTiming);
        cudaEventCreateWithFlags(&s_scal, cudaEventDisableTiming);
    }

    int gm = (n + 127) / 128;
    int ga = (int)(((long long)n * 32 + 255) / 256);
    int gn = (n + 255) / 256;
    int ge = (e + 255) / 256;

    // side: zero -> count -> scatter; later scalar aggs (need dis from main)
    cudaEventRecord(s_fork, 0);
    cudaStreamWaitEvent(s_side, s_fork, 0);
    k_zero<<<gn, 256, 0, s_side>>>(n);
    k_count<<<ge, 256, 0, s_side>>>(dstp, e);
    cudaEventRecord(s_cnt, s_side);                 // cnt ready (for dis on main)
    k_scatter<<<ge, 256, 0, s_side>>>(src, dstp, e);
    cudaEventRecord(s_csr, s_side);                 // CSR ready

    // main: weight collapse runs during count; gemm chain = dis -> gemm
    k_mm128<<<64, 256>>>(W0, W1, Wtp);
    k_mm128<<<64, 256>>>(Wtp, W2, W012p);
    k_cvec<<<1, 128>>>(b0, b1, W1, W2);
    cudaStreamWaitEvent(0, s_cnt, 0);
    k_dis<<<gn, 256>>>(n);
    cudaEventRecord(s_disv, 0);
    k_gemm<<<gm, 256>>>(feat, W012p, Hp, n);

    // side continues: scalar aggs need dis + CSR; overlap with gemm tail / agg_mid0
    cudaStreamWaitEvent(s_side, s_disv, 0);
    k_aggs1<<<gn, 256, 0, s_side>>>(n);
    k_aggs2<<<gn, 256, 0, s_side>>>(n);
    cudaEventRecord(s_scal, s_side);

    // aggregations: mids need CSR + G0; fin additionally needs u1/u2
    cudaStreamWaitEvent(0, s_csr, 0);
    k_agg_mid<<<ga, 256>>>(Hp, Ap, n);
    k_agg_mid<<<ga, 256>>>(Ap, Hp, n);
    cudaStreamWaitEvent(0, s_scal, 0);
    k_agg_fin<<<ga, 256>>>(Hp, b2, (float*)d_out, n);
}

// round 15
// speedup vs baseline: 1.1402x; 1.1402x over previous
#include <cuda_runtime.h>
#include <cuda_fp16.h>
#include <cstdint>
#include <cstddef>

#define NMAX 100000
#define EMAX 1600000
#define D 128

// ---------------- static device scratch ----------------
__device__ __half g_H[(size_t)NMAX * D];    // ping buffer, fp16 (pre-scaled G)
__device__ __half g_A[(size_t)NMAX * D];    // pong buffer, fp16
__device__ int    g_cnt[NMAX];
__device__ float  g_dis[NMAX];
__device__ int    g_rs[NMAX + 1];
__device__ int    g_cur[NMAX];
__device__ volatile int g_sflag[128];       // fused-scan flags (value = tile_sum + 1)
__device__ int    g_csrs[EMAX];
__device__ float  g_Wt[128 * 128];          // W0*W1
__device__ float  g_W012[128 * 128];        // W0*W1*W2
__device__ float  g_c1[128];                // b0*W1*W2
__device__ float  g_c2[128];                // b1*W2
__device__ float  g_u1[NMAX];               // A*1
__device__ float  g_t1[NMAX];               // dis * u1
__device__ float  g_u2[NMAX];               // A^2*1

// ---------------- graph preprocessing ----------------
__global__ void k_zero(int n) {
    int i = blockIdx.x * blockDim.x + threadIdx.x;
    if (i < n) g_cnt[i] = 0;
    if (i < 128) g_sflag[i] = 0;
}

__global__ void k_count(const int* __restrict__ dst, int e) {
    int i = blockIdx.x * blockDim.x + threadIdx.x;
    if (i < e) atomicAdd(&g_cnt[dst[i]], 1);
}

// fused single-pass scan (all 98 blocks resident): tile scan + value-carrying flags
__global__ void k_scan(int n, int e) {
    __shared__ int sm[1024];
    __shared__ int red[128];
    int b = blockIdx.x, t = threadIdx.x;
    int i = b * 1024 + t;
    int v = (i < n) ? g_cnt[i] : 0;
    sm[t] = v;
    __syncthreads();
    for (int off = 1; off < 1024; off <<= 1) {
        int tt = (t >= (unsigned)off) ? sm[t - off] : 0;
        __syncthreads();
        sm[t] += tt;
        __syncthreads();
    }
    if (t == 1023) g_sflag[b] = sm[1023] + 1;

    if (t < 128) {
        int val = 0;
        if (t < b) {
            int f;
            while ((f = g_sflag[t]) == 0) { }
            val = f - 1;
        }
        red[t] = val;
    }
    __syncthreads();
    for (int off = 64; off > 0; off >>= 1) {
        if (t < (unsigned)off) red[t] += red[t + off];
        __syncthreads();
    }
    int pre = red[0];
    if (i < n) {
        int ex = sm[t] - v + pre;
        g_rs[i] = ex;
        g_cur[i] = ex;
        g_dis[i] = rsqrtf((float)(g_cnt[i] + 1));
    }
    if (i == 0) g_rs[n] = e;
}

// vectorized index-only scatter: 4 edges per thread
__global__ void k_scatter(const int* __restrict__ src, const int* __restrict__ dst, int e) {
    int i = (blockIdx.x * blockDim.x + threadIdx.x) * 4;
    if (i + 4 <= e) {
        int4 s4 = *(const int4*)(src + i);
        int4 d4 = *(const int4*)(dst + i);
        int p0 = atomicAdd(&g_cur[d4.x], 1);
        int p1 = atomicAdd(&g_cur[d4.y], 1);
        int p2 = atomicAdd(&g_cur[d4.z], 1);
        int p3 = atomicAdd(&g_cur[d4.w], 1);
        g_csrs[p0] = s4.x;
        g_csrs[p1] = s4.y;
        g_csrs[p2] = s4.z;
        g_csrs[p3] = s4.w;
    } else {
        for (; i < e; i++) {
            int d = dst[i];
            int p = atomicAdd(&g_cur[d], 1);
            g_csrs[p] = src[i];
        }
    }
}

// ---------------- fast 128x128 fp32 matmul: C = A*B ----------------
// 64 blocks x 256 threads; block covers 2 rows; A rows staged in smem;
// 4 split accumulators + full unroll -> 128 independent B loads in flight.
__global__ void __launch_bounds__(256) k_mm128(const float* __restrict__ A,
                                               const float* __restrict__ B,
                                               float* __restrict__ C) {
    __shared__ float sA[2][128];
    int b = blockIdx.x, t = threadIdx.x;
    int r0 = b * 2;
    if (t < 64) {
        ((float4*)sA[0])[t & 31] = ((const float4*)(A + (size_t)r0 * 128))[t & 31];
    } else if (t < 128) {
        ((float4*)sA[1])[t & 31] = ((const float4*)(A + (size_t)(r0 + 1) * 128))[t & 31];
    }
    __syncthreads();
    int rr = t >> 7;         // 0 or 1
    int c = t & 127;
    float a0 = 0, a1 = 0, a2 = 0, a3 = 0;
#pragma unroll
    for (int k = 0; k < 128; k += 4) {
        float w0 = B[(k + 0) * 128 + c];
        float w1 = B[(k + 1) * 128 + c];
        float w2 = B[(k + 2) * 128 + c];
        float w3 = B[(k + 3) * 128 + c];
        a0 = fmaf(sA[rr][k + 0], w0, a0);
        a1 = fmaf(sA[rr][k + 1], w1, a1);
        a2 = fmaf(sA[rr][k + 2], w2, a2);
        a3 = fmaf(sA[rr][k + 3], w3, a3);
    }
    C[(size_t)(r0 + rr) * 128 + c] = (a0 + a1) + (a2 + a3);
}

// ---------------- bias correction vectors: c1 = b0*W1*W2, c2 = b1*W2 ----------------
__global__ void k_cvec(const float* __restrict__ b0, const float* __restrict__ b1,
                       const float* __restrict__ W1, const float* __restrict__ W2) {
    __shared__ float t1[128];
    int j = threadIdx.x;
    float s = 0.0f;
    for (int k = 0; k < 128; k++) s = fmaf(b0[k], W1[k * 128 + j], s);
    t1[j] = s;
    __syncthreads();
    float s1 = 0.0f, s2 = 0.0f;
    for (int k = 0; k < 128; k++) {
        float w = W2[k * 128 + j];
        s1 = fmaf(t1[k], w, s1);
        s2 = fmaf(b1[k], w, s2);
    }
    g_c1[j] = s1;
    g_c2[j] = s2;
}

// ---------------- scalar aggregations (weight-free form) ----------------
__global__ void k_aggs1(int n) {
    int v = blockIdx.x * blockDim.x + threadIdx.x;
    if (v >= n) return;
    float dv = g_dis[v];
    float s = dv;
    int end = g_rs[v + 1];
    for (int e = g_rs[v]; e < end; e++) s += g_dis[g_csrs[e]];
    float u1 = dv * s;
    g_u1[v] = u1;
    g_t1[v] = dv * u1;
}

__global__ void k_aggs2(int n) {
    int v = blockIdx.x * blockDim.x + threadIdx.x;
    if (v >= n) return;
    float dv = g_dis[v];
    float s = g_t1[v];
    int end = g_rs[v + 1];
    for (int e = g_rs[v]; e < end; e++) s += g_t1[g_csrs[e]];
    g_u2[v] = dv * s;
}

// ---------------- MMA helpers ----------------
__device__ __forceinline__ void mma_f16(float* c, const unsigned* a, unsigned b0, unsigned b1) {
    asm volatile(
        "mma.sync.aligned.m16n8k16.row.col.f32.f16.f16.f32 "
        "{%0,%1,%2,%3}, {%4,%5,%6,%7}, {%8,%9}, {%0,%1,%2,%3};\n"
        : "+f"(c[0]), "+f"(c[1]), "+f"(c[2]), "+f"(c[3])
        : "r"(a[0]), "r"(a[1]), "r"(a[2]), "r"(a[3]), "r"(b0), "r"(b1));
}

#define BSTR 136

// ---------------- GEMM: G0 = diag(dis) * (X @ W012), fp16 out ----------------
__global__ void __launch_bounds__(256)
k_gemm(const float* __restrict__ X, const float* __restrict__ W,
       __half* __restrict__ H, int n) {
    __shared__ unsigned Bh[64 * BSTR];

    int tid = threadIdx.x;
    for (int i = tid; i < 64 * 128; i += 256) {
        int j = i >> 7, c = i & 127;
        float w0 = W[(2 * j) * 128 + c];
        float w1 = W[(2 * j + 1) * 128 + c];
        __half2 h = __floats2half2_rn(w0, w1);
        Bh[j * BSTR + c] = *(unsigned*)&h;
    }
    __syncthreads();

    int wid = tid >> 5, lane = tid & 31;
    int warp_m = wid >> 1, warp_n = wid & 1;
    int g = lane >> 2, tg = lane & 3;
    int rbase = blockIdx.x * 128 + warp_m * 32;
    int cbase = warp_n * 64;
    int nclamp = n - 1;

    float acc[2][8][4];
#pragma unroll
    for (int mf = 0; mf < 2; mf++)
#pragma unroll
        for (int nt = 0; nt < 8; nt++)
#pragma unroll
            for (int q = 0; q < 4; q++) acc[mf][nt][q] = 0.0f;

    for (int k0 = 0; k0 < 128; k0 += 16) {
        unsigned a[2][4];
#pragma unroll
        for (int mf = 0; mf < 2; mf++) {
            int r0 = rbase + mf * 16 + g;
            int r1 = r0 + 8;
            if (r0 > nclamp) r0 = nclamp;
            if (r1 > nclamp) r1 = nclamp;
            const float* p0 = X + (size_t)r0 * D + k0 + 2 * tg;
            const float* p1 = X + (size_t)r1 * D + k0 + 2 * tg;
            float2 f00 = *(const float2*)(p0);
            float2 f01 = *(const float2*)(p0 + 8);
            float2 f10 = *(const float2*)(p1);
            float2 f11 = *(const float2*)(p1 + 8);
            __half2 h0 = __floats2half2_rn(f00.x, f00.y);
            __half2 h1 = __floats2half2_rn(f10.x, f10.y);
            __half2 h2 = __floats2half2_rn(f01.x, f01.y);
            __half2 h3 = __floats2half2_rn(f11.x, f11.y);
            a[mf][0] = *(unsigned*)&h0;
            a[mf][1] = *(unsigned*)&h1;
            a[mf][2] = *(unsigned*)&h2;
            a[mf][3] = *(unsigned*)&h3;
        }
#pragma unroll
        for (int nt = 0; nt < 8; nt++) {
            int c = cbase + nt * 8 + g;
            int i0 = (k0 / 2 + tg) * BSTR + c;
            int i1 = i0 + 4 * BSTR;
            unsigned b0 = Bh[i0], b1 = Bh[i1];
#pragma unroll
            for (int mf = 0; mf < 2; mf++)
                mma_f16(acc[mf][nt], a[mf], b0, b1);
        }
    }

#pragma unroll
    for (int mf = 0; mf < 2; mf++) {
        int r0 = rbase + mf * 16 + g;
        int r1 = r0 + 8;
        float d0 = (r0 < n) ? g_dis[r0] : 0.0f;
        float d1 = (r1 < n) ? g_dis[r1] : 0.0f;
#pragma unroll
        for (int nt = 0; nt < 8; nt++) {
            int c = cbase + nt * 8 + 2 * tg;
            if (r0 < n) {
                __half2 v = __floats2half2_rn(d0 * acc[mf][nt][0], d0 * acc[mf][nt][1]);
                *(__half2*)(H + (size_t)r0 * D + c) = v;
            }
            if (r1 < n) {
                __half2 v = __floats2half2_rn(d1 * acc[mf][nt][2], d1 * acc[mf][nt][3]);
                *(__half2*)(H + (size_t)r1 * D + c) = v;
            }
        }
    }
}

// ---------------- aggregation: weight-free sum of pre-scaled rows ----------------
__device__ __forceinline__ void unpack_add8(float* acc, uint4 u) {
    float2 p0 = __half22float2(*(__half2*)&u.x);
    float2 p1 = __half22float2(*(__half2*)&u.y);
    float2 p2 = __half22float2(*(__half2*)&u.z);
    float2 p3 = __half22float2(*(__half2*)&u.w);
    acc[0] += p0.x; acc[1] += p0.y;
    acc[2] += p1.x; acc[3] += p1.y;
    acc[4] += p2.x; acc[5] += p2.y;
    acc[6] += p3.x; acc[7] += p3.y;
}

__device__ __forceinline__ void agg_sum(const uint4* __restrict__ H4, int node,
                                        int half, int c16, float* acc) {
#pragma unroll
    for (int i = 0; i < 8; i++) acc[i] = 0.0f;

    if (half == 0) {
        uint4 uv = H4[(size_t)node * 16 + c16];
        unpack_add8(acc, uv);
    }

    int e = g_rs[node], end = g_rs[node + 1];
    for (; e + 8 <= end; e += 8) {
        int i0 = e + half, i1 = e + 2 + half, i2 = e + 4 + half, i3 = e + 6 + half;
        int s0 = g_csrs[i0], s1 = g_csrs[i1], s2 = g_csrs[i2], s3 = g_csrs[i3];
        uint4 u0 = H4[(size_t)s0 * 16 + c16];
        uint4 u1 = H4[(size_t)s1 * 16 + c16];
        uint4 u2 = H4[(size_t)s2 * 16 + c16];
        uint4 u3 = H4[(size_t)s3 * 16 + c16];
        unpack_add8(acc, u0);
        unpack_add8(acc, u1);
        unpack_add8(acc, u2);
        unpack_add8(acc, u3);
    }
    for (; e < end; e += 2) {
        int idx = e + half;
        if (idx < end) {
            uint4 u = H4[(size_t)g_csrs[idx] * 16 + c16];
            unpack_add8(acc, u);
        }
    }
#pragma unroll
    for (int i = 0; i < 8; i++)
        acc[i] += __shfl_xor_sync(0xffffffffu, acc[i], 16);
}

__global__ void k_agg_mid(const __half* __restrict__ Hh, __half* __restrict__ Oh, int n) {
    int warp = (blockIdx.x * blockDim.x + threadIdx.x) >> 5;
    int lane = threadIdx.x & 31;
    if (warp >= n) return;
    int half = lane >> 4, c16 = lane & 15;

    float acc[8];
    agg_sum((const uint4*)Hh, warp, half, c16, acc);

    if (half == 0) {
        float dv = g_dis[warp];
        float s2 = dv * dv;
        __half2 h0 = __floats2half2_rn(s2 * acc[0], s2 * acc[1]);
        __half2 h1 = __floats2half2_rn(s2 * acc[2], s2 * acc[3]);
        __half2 h2 = __floats2half2_rn(s2 * acc[4], s2 * acc[5]);
        __half2 h3 = __floats2half2_rn(s2 * acc[6], s2 * acc[7]);
        uint4 o;
        o.x = *(unsigned*)&h0;
        o.y = *(unsigned*)&h1;
        o.z = *(unsigned*)&h2;
        o.w = *(unsigned*)&h3;
        ((uint4*)Oh)[(size_t)warp * 16 + c16] = o;
    }
}

__global__ void k_agg_fin(const __half* __restrict__ Hh, const float* __restrict__ b2,
                          float* __restrict__ out, int n) {
    int warp = (blockIdx.x * blockDim.x + threadIdx.x) >> 5;
    int lane = threadIdx.x & 31;
    if (warp >= n) return;
    int half = lane >> 4, c16 = lane & 15;

    float acc[8];
    agg_sum((const uint4*)Hh, warp, half, c16, acc);

    if (half == 0) {
        float dv  = g_dis[warp];
        float u2v = g_u2[warp];
        float u1v = g_u1[warp];
        float4 c1a = ((const float4*)g_c1)[c16 * 2];
        float4 c1b = ((const float4*)g_c1)[c16 * 2 + 1];
        float4 c2a = ((const float4*)g_c2)[c16 * 2];
        float4 c2b = ((const float4*)g_c2)[c16 * 2 + 1];
        float4 ba  = ((const float4*)b2)[c16 * 2];
        float4 bb  = ((const float4*)b2)[c16 * 2 + 1];

        float4 oa, ob;
        oa.x = dv * acc[0] + u2v * c1a.x + u1v * c2a.x + ba.x;
        oa.y = dv * acc[1] + u2v * c1a.y + u1v * c2a.y + ba.y;
        oa.z = dv * acc[2] + u2v * c1a.z + u1v * c2a.z + ba.z;
        oa.w = dv * acc[3] + u2v * c1a.w + u1v * c2a.w + ba.w;
        ob.x = dv * acc[4] + u2v * c1b.x + u1v * c2b.x + bb.x;
        ob.y = dv * acc[5] + u2v * c1b.y + u1v * c2b.y + bb.y;
        ob.z = dv * acc[6] + u2v * c1b.z + u1v * c2b.z + bb.z;
        ob.w = dv * acc[7] + u2v * c1b.w + u1v * c2b.w + bb.w;
        ((float4*)out)[(size_t)warp * 32 + c16 * 2]     = oa;
        ((float4*)out)[(size_t)warp * 32 + c16 * 2 + 1] = ob;
    }
}

// ---------------- launch: 3 streams (main graph/agg, W-collapse, CSR tail) ----------------
extern "C" void kernel_launch(void* const* d_in, const int* in_sizes, int n_in,
                              void* d_out, int out_size) {
    const float* feat = (const float*)d_in[0];
    const int*   ei   = (const int*)d_in[1];
    const float* W0 = (const float*)d_in[2];
    const float* b0 = (const float*)d_in[3];
    const float* W1 = (const float*)d_in[4];
    const float* b1 = (const float*)d_in[5];
    const float* W2 = (const float*)d_in[6];
    const float* b2 = (const float*)d_in[7];

    int n = in_sizes[0] / D;
    int e = in_sizes[1] / 2;
    if (n > NMAX) n = NMAX;
    if (e > EMAX) e = EMAX;
    const int* src = ei;
    const int* dstp = ei + e;

    __half *Hp, *Ap;
    float *Wtp, *W012p;
    cudaGetSymbolAddress((void**)&Hp, g_H);
    cudaGetSymbolAddress((void**)&Ap, g_A);
    cudaGetSymbolAddress((void**)&Wtp, g_Wt);
    cudaGetSymbolAddress((void**)&W012p, g_W012);

    static cudaStream_t sW = nullptr, sE = nullptr;
    static cudaEvent_t  eFork = nullptr, eW = nullptr, eDis = nullptr,
                        eCsr = nullptr, eScal = nullptr;
    if (!sW) {
        cudaStreamCreateWithFlags(&sW, cudaStreamNonBlocking);
        cudaStreamCreateWithFlags(&sE, cudaStreamNonBlocking);
        cudaEventCreateWithFlags(&eFork, cudaEventDisableTiming);
        cudaEventCreateWithFlags(&eW, cudaEventDisableTiming);
        cudaEventCreateWithFlags(&eDis, cudaEventDisableTiming);
        cudaEventCreateWithFlags(&eCsr, cudaEventDisableTiming);
        cudaEventCreateWithFlags(&eScal, cudaEventDisableTiming);
    }

    int nb = (n + 1023) / 1024;
    int gm = (n + 127) / 128;
    int ga = (int)(((long long)n * 32 + 255) / 256);
    int gn = (n + 255) / 256;
    int ge = (e + 255) / 256;
    int ge4 = (e + 1023) / 1024;

    cudaEventRecord(eFork, 0);

    // stream W: weight collapse (independent of graph)
    cudaStreamWaitEvent(sW, eFork, 0);
    k_mm128<<<64, 256, 0, sW>>>(W0, W1, Wtp);
    k_mm128<<<64, 256, 0, sW>>>(Wtp, W2, W012p);
    k_cvec<<<1, 128, 0, sW>>>(b0, b1, W1, W2);
    cudaEventRecord(eW, sW);

    // main: graph head (zero -> count -> fused scan incl. dis)
    k_zero<<<gn, 256>>>(n);
    k_count<<<ge, 256>>>(dstp, e);
    k_scan<<<nb, 1024>>>(n, e);
    cudaEventRecord(eDis, 0);

    // stream E: scatter + scalar aggs (need scan results)
    cudaStreamWaitEvent(sE, eDis, 0);
    k_scatter<<<ge4, 256, 0, sE>>>(src, dstp, e);
    cudaEventRecord(eCsr, sE);
    k_aggs1<<<gn, 256, 0, sE>>>(n);
    k_aggs2<<<gn, 256, 0, sE>>>(n);
    cudaEventRecord(eScal, sE);

    // main: gemm (needs dis from scan, W012 from sW)
    cudaStreamWaitEvent(0, eW, 0);
    k_gemm<<<gm, 256>>>(feat, W012p, Hp, n);

    // aggregations: mids need CSR + G0; fin additionally needs u1/u2
    cudaStreamWaitEvent(0, eCsr, 0);
    k_agg_mid<<<ga, 256>>>(Hp, Ap, n);
    k_agg_mid<<<ga, 256>>>(Ap, Hp, n);
    cudaStreamWaitEvent(0, eScal, 0);
    k_agg_fin<<<ga, 256>>>(Hp, b2, (float*)d_out, n);
}

// round 16
// speedup vs baseline: 1.1481x; 1.0069x over previous
#include <cuda_runtime.h>
#include <cuda_fp16.h>
#include <cstdint>
#include <cstddef>

#define NMAX 100000
#define EMAX 1600000
#define D 128

// ---------------- static device scratch ----------------
// g_cnt and g_sflag are zero-initialized at module load and re-zeroed by
// k_ztail at the END of every launch (tail-zeroing) — never zeroed up front.
__device__ __half g_H[(size_t)NMAX * D];    // ping buffer, fp16 (pre-scaled G)
__device__ __half g_A[(size_t)NMAX * D];    // pong buffer, fp16
__device__ int    g_cnt[NMAX];
__device__ float  g_dis[NMAX];
__device__ int    g_rs[NMAX + 1];
__device__ int    g_cur[NMAX];
__device__ volatile int g_sflag[128];       // fused-scan flags (value = tile_sum + 1)
__device__ int    g_csrs[EMAX];
__device__ float  g_Wt[128 * 128];          // W0*W1
__device__ float  g_W012[128 * 128];        // W0*W1*W2
__device__ float  g_c1[128];                // b0*W1*W2
__device__ float  g_c2[128];                // b1*W2
__device__ float  g_u1[NMAX];               // A*1
__device__ float  g_t1[NMAX];               // dis * u1
__device__ float  g_u2[NMAX];               // A^2*1

// ---------------- graph preprocessing ----------------
// vectorized degree count: 4 edges per thread
__global__ void k_count(const int* __restrict__ dst, int e) {
    int i = (blockIdx.x * blockDim.x + threadIdx.x) * 4;
    if (i + 4 <= e) {
        int4 d4 = *(const int4*)(dst + i);
        atomicAdd(&g_cnt[d4.x], 1);
        atomicAdd(&g_cnt[d4.y], 1);
        atomicAdd(&g_cnt[d4.z], 1);
        atomicAdd(&g_cnt[d4.w], 1);
    } else {
        for (; i < e; i++) atomicAdd(&g_cnt[dst[i]], 1);
    }
}

// fused single-pass scan (all 98 blocks resident): tile scan + value-carrying flags
__global__ void k_scan(int n, int e) {
    __shared__ int sm[1024];
    __shared__ int red[128];
    int b = blockIdx.x, t = threadIdx.x;
    int i = b * 1024 + t;
    int v = (i < n) ? g_cnt[i] : 0;
    sm[t] = v;
    __syncthreads();
    for (int off = 1; off < 1024; off <<= 1) {
        int tt = (t >= (unsigned)off) ? sm[t - off] : 0;
        __syncthreads();
        sm[t] += tt;
        __syncthreads();
    }
    if (t == 1023) g_sflag[b] = sm[1023] + 1;

    if (t < 128) {
        int val = 0;
        if (t < b) {
            int f;
            while ((f = g_sflag[t]) == 0) { }
            val = f - 1;
        }
        red[t] = val;
    }
    __syncthreads();
    for (int off = 64; off > 0; off >>= 1) {
        if (t < (unsigned)off) red[t] += red[t + off];
        __syncthreads();
    }
    int pre = red[0];
    if (i < n) {
        int ex = sm[t] - v + pre;
        g_rs[i] = ex;
        g_cur[i] = ex;
        g_dis[i] = rsqrtf((float)(g_cnt[i] + 1));
    }
    if (i == 0) g_rs[n] = e;
}

// tail zeroing for next replay (runs off the critical path)
__global__ void k_ztail(int n) {
    int i = blockIdx.x * blockDim.x + threadIdx.x;
    if (i < n) g_cnt[i] = 0;
    if (i < 128) g_sflag[i] = 0;
}

// vectorized index-only scatter: 4 edges per thread
__global__ void k_scatter(const int* __restrict__ src, const int* __restrict__ dst, int e) {
    int i = (blockIdx.x * blockDim.x + threadIdx.x) * 4;
    if (i + 4 <= e) {
        int4 s4 = *(const int4*)(src + i);
        int4 d4 = *(const int4*)(dst + i);
        int p0 = atomicAdd(&g_cur[d4.x], 1);
        int p1 = atomicAdd(&g_cur[d4.y], 1);
        int p2 = atomicAdd(&g_cur[d4.z], 1);
        int p3 = atomicAdd(&g_cur[d4.w], 1);
        g_csrs[p0] = s4.x;
        g_csrs[p1] = s4.y;
        g_csrs[p2] = s4.z;
        g_csrs[p3] = s4.w;
    } else {
        for (; i < e; i++) {
            int d = dst[i];
            int p = atomicAdd(&g_cur[d], 1);
            g_csrs[p] = src[i];
        }
    }
}

// ---------------- fast 128x128 fp32 matmul: C = A*B ----------------
__global__ void __launch_bounds__(256) k_mm128(const float* __restrict__ A,
                                               const float* __restrict__ B,
                                               float* __restrict__ C) {
    __shared__ float sA[2][128];
    int b = blockIdx.x, t = threadIdx.x;
    int r0 = b * 2;
    if (t < 64) {
        ((float4*)sA[0])[t & 31] = ((const float4*)(A + (size_t)r0 * 128))[t & 31];
    } else if (t < 128) {
        ((float4*)sA[1])[t & 31] = ((const float4*)(A + (size_t)(r0 + 1) * 128))[t & 31];
    }
    __syncthreads();
    int rr = t >> 7;
    int c = t & 127;
    float a0 = 0, a1 = 0, a2 = 0, a3 = 0;
#pragma unroll
    for (int k = 0; k < 128; k += 4) {
        float w0 = B[(k + 0) * 128 + c];
        float w1 = B[(k + 1) * 128 + c];
        float w2 = B[(k + 2) * 128 + c];
        float w3 = B[(k + 3) * 128 + c];
        a0 = fmaf(sA[rr][k + 0], w0, a0);
        a1 = fmaf(sA[rr][k + 1], w1, a1);
        a2 = fmaf(sA[rr][k + 2], w2, a2);
        a3 = fmaf(sA[rr][k + 3], w3, a3);
    }
    C[(size_t)(r0 + rr) * 128 + c] = (a0 + a1) + (a2 + a3);
}

// ---------------- bias correction vectors: c1 = b0*W1*W2, c2 = b1*W2 ----------------
__global__ void k_cvec(const float* __restrict__ b0, const float* __restrict__ b1,
                       const float* __restrict__ W1, const float* __restrict__ W2) {
    __shared__ float t1[128];
    int j = threadIdx.x;
    float s = 0.0f;
    for (int k = 0; k < 128; k++) s = fmaf(b0[k], W1[k * 128 + j], s);
    t1[j] = s;
    __syncthreads();
    float s1 = 0.0f, s2 = 0.0f;
    for (int k = 0; k < 128; k++) {
        float w = W2[k * 128 + j];
        s1 = fmaf(t1[k], w, s1);
        s2 = fmaf(b1[k], w, s2);
    }
    g_c1[j] = s1;
    g_c2[j] = s2;
}

// ---------------- scalar aggregations (weight-free form) ----------------
__global__ void k_aggs1(int n) {
    int v = blockIdx.x * blockDim.x + threadIdx.x;
    if (v >= n) return;
    float dv = g_dis[v];
    float s = dv;
    int end = g_rs[v + 1];
    for (int e = g_rs[v]; e < end; e++) s += g_dis[g_csrs[e]];
    float u1 = dv * s;
    g_u1[v] = u1;
    g_t1[v] = dv * u1;
}

__global__ void k_aggs2(int n) {
    int v = blockIdx.x * blockDim.x + threadIdx.x;
    if (v >= n) return;
    float dv = g_dis[v];
    float s = g_t1[v];
    int end = g_rs[v + 1];
    for (int e = g_rs[v]; e < end; e++) s += g_t1[g_csrs[e]];
    g_u2[v] = dv * s;
}

// ---------------- MMA helpers ----------------
__device__ __forceinline__ void mma_f16(float* c, const unsigned* a, unsigned b0, unsigned b1) {
    asm volatile(
        "mma.sync.aligned.m16n8k16.row.col.f32.f16.f16.f32 "
        "{%0,%1,%2,%3}, {%4,%5,%6,%7}, {%8,%9}, {%0,%1,%2,%3};\n"
        : "+f"(c[0]), "+f"(c[1]), "+f"(c[2]), "+f"(c[3])
        : "r"(a[0]), "r"(a[1]), "r"(a[2]), "r"(a[3]), "r"(b0), "r"(b1));
}

#define BSTR 136

// ---------------- GEMM: G0 = diag(dis) * (X @ W012), fp16 out ----------------
__global__ void __launch_bounds__(256)
k_gemm(const float* __restrict__ X, const float* __restrict__ W,
       __half* __restrict__ H, int n) {
    __shared__ unsigned Bh[64 * BSTR];

    int tid = threadIdx.x;
    for (int i = tid; i < 64 * 128; i += 256) {
        int j = i >> 7, c = i & 127;
        float w0 = W[(2 * j) * 128 + c];
        float w1 = W[(2 * j + 1) * 128 + c];
        __half2 h = __floats2half2_rn(w0, w1);
        Bh[j * BSTR + c] = *(unsigned*)&h;
    }
    __syncthreads();

    int wid = tid >> 5, lane = tid & 31;
    int warp_m = wid >> 1, warp_n = wid & 1;
    int g = lane >> 2, tg = lane & 3;
    int rbase = blockIdx.x * 128 + warp_m * 32;
    int cbase = warp_n * 64;
    int nclamp = n - 1;

    float acc[2][8][4];
#pragma unroll
    for (int mf = 0; mf < 2; mf++)
#pragma unroll
        for (int nt = 0; nt < 8; nt++)
#pragma unroll
            for (int q = 0; q < 4; q++) acc[mf][nt][q] = 0.0f;

    for (int k0 = 0; k0 < 128; k0 += 16) {
        unsigned a[2][4];
#pragma unroll
        for (int mf = 0; mf < 2; mf++) {
            int r0 = rbase + mf * 16 + g;
            int r1 = r0 + 8;
            if (r0 > nclamp) r0 = nclamp;
            if (r1 > nclamp) r1 = nclamp;
            const float* p0 = X + (size_t)r0 * D + k0 + 2 * tg;
            const float* p1 = X + (size_t)r1 * D + k0 + 2 * tg;
            float2 f00 = *(const float2*)(p0);
            float2 f01 = *(const float2*)(p0 + 8);
            float2 f10 = *(const float2*)(p1);
            float2 f11 = *(const float2*)(p1 + 8);
            __half2 h0 = __floats2half2_rn(f00.x, f00.y);
            __half2 h1 = __floats2half2_rn(f10.x, f10.y);
            __half2 h2 = __floats2half2_rn(f01.x, f01.y);
            __half2 h3 = __floats2half2_rn(f11.x, f11.y);
            a[mf][0] = *(unsigned*)&h0;
            a[mf][1] = *(unsigned*)&h1;
            a[mf][2] = *(unsigned*)&h2;
            a[mf][3] = *(unsigned*)&h3;
        }
#pragma unroll
        for (int nt = 0; nt < 8; nt++) {
            int c = cbase + nt * 8 + g;
            int i0 = (k0 / 2 + tg) * BSTR + c;
            int i1 = i0 + 4 * BSTR;
            unsigned b0 = Bh[i0], b1 = Bh[i1];
#pragma unroll
            for (int mf = 0; mf < 2; mf++)
                mma_f16(acc[mf][nt], a[mf], b0, b1);
        }
    }

#pragma unroll
    for (int mf = 0; mf < 2; mf++) {
        int r0 = rbase + mf * 16 + g;
        int r1 = r0 + 8;
        float d0 = (r0 < n) ? g_dis[r0] : 0.0f;
        float d1 = (r1 < n) ? g_dis[r1] : 0.0f;
#pragma unroll
        for (int nt = 0; nt < 8; nt++) {
            int c = cbase + nt * 8 + 2 * tg;
            if (r0 < n) {
                __half2 v = __floats2half2_rn(d0 * acc[mf][nt][0], d0 * acc[mf][nt][1]);
                *(__half2*)(H + (size_t)r0 * D + c) = v;
            }
            if (r1 < n) {
                __half2 v = __floats2half2_rn(d1 * acc[mf][nt][2], d1 * acc[mf][nt][3]);
                *(__half2*)(H + (size_t)r1 * D + c) = v;
            }
        }
    }
}

// ---------------- aggregation: weight-free sum of pre-scaled rows ----------------
__device__ __forceinline__ void unpack_add8(float* acc, uint4 u) {
    float2 p0 = __half22float2(*(__half2*)&u.x);
    float2 p1 = __half22float2(*(__half2*)&u.y);
    float2 p2 = __half22float2(*(__half2*)&u.z);
    float2 p3 = __half22float2(*(__half2*)&u.w);
    acc[0] += p0.x; acc[1] += p0.y;
    acc[2] += p1.x; acc[3] += p1.y;
    acc[4] += p2.x; acc[5] += p2.y;
    acc[6] += p3.x; acc[7] += p3.y;
}

__device__ __forceinline__ void agg_sum(const uint4* __restrict__ H4, int node,
                                        int half, int c16, float* acc) {
#pragma unroll
    for (int i = 0; i < 8; i++) acc[i] = 0.0f;

    if (half == 0) {
        uint4 uv = H4[(size_t)node * 16 + c16];
        unpack_add8(acc, uv);
    }

    int e = g_rs[node], end = g_rs[node + 1];
    for (; e + 8 <= end; e += 8) {
        int i0 = e + half, i1 = e + 2 + half, i2 = e + 4 + half, i3 = e + 6 + half;
        int s0 = g_csrs[i0], s1 = g_csrs[i1], s2 = g_csrs[i2], s3 = g_csrs[i3];
        uint4 u0 = H4[(size_t)s0 * 16 + c16];
        uint4 u1 = H4[(size_t)s1 * 16 + c16];
        uint4 u2 = H4[(size_t)s2 * 16 + c16];
        uint4 u3 = H4[(size_t)s3 * 16 + c16];
        unpack_add8(acc, u0);
        unpack_add8(acc, u1);
        unpack_add8(acc, u2);
        unpack_add8(acc, u3);
    }
    for (; e < end; e += 2) {
        int idx = e + half;
        if (idx < end) {
            uint4 u = H4[(size_t)g_csrs[idx] * 16 + c16];
            unpack_add8(acc, u);
        }
    }
#pragma unroll
    for (int i = 0; i < 8; i++)
        acc[i] += __shfl_xor_sync(0xffffffffu, acc[i], 16);
}

__global__ void k_agg_mid(const __half* __restrict__ Hh, __half* __restrict__ Oh, int n) {
    int warp = (blockIdx.x * blockDim.x + threadIdx.x) >> 5;
    int lane = threadIdx.x & 31;
    if (warp >= n) return;
    int half = lane >> 4, c16 = lane & 15;

    float acc[8];
    agg_sum((const uint4*)Hh, warp, half, c16, acc);

    if (half == 0) {
        float dv = g_dis[warp];
        float s2 = dv * dv;
        __half2 h0 = __floats2half2_rn(s2 * acc[0], s2 * acc[1]);
        __half2 h1 = __floats2half2_rn(s2 * acc[2], s2 * acc[3]);
        __half2 h2 = __floats2half2_rn(s2 * acc[4], s2 * acc[5]);
        __half2 h3 = __floats2half2_rn(s2 * acc[6], s2 * acc[7]);
        uint4 o;
        o.x = *(unsigned*)&h0;
        o.y = *(unsigned*)&h1;
        o.z = *(unsigned*)&h2;
        o.w = *(unsigned*)&h3;
        ((uint4*)Oh)[(size_t)warp * 16 + c16] = o;
    }
}

__global__ void k_agg_fin(const __half* __restrict__ Hh, const float* __restrict__ b2,
                          float* __restrict__ out, int n) {
    int warp = (blockIdx.x * blockDim.x + threadIdx.x) >> 5;
    int lane = threadIdx.x & 31;
    if (warp >= n) return;
    int half = lane >> 4, c16 = lane & 15;

    float acc[8];
    agg_sum((const uint4*)Hh, warp, half, c16, acc);

    if (half == 0) {
        float dv  = g_dis[warp];
        float u2v = g_u2[warp];
        float u1v = g_u1[warp];
        float4 c1a = ((const float4*)g_c1)[c16 * 2];
        float4 c1b = ((const float4*)g_c1)[c16 * 2 + 1];
        float4 c2a = ((const float4*)g_c2)[c16 * 2];
        float4 c2b = ((const float4*)g_c2)[c16 * 2 + 1];
        float4 ba  = ((const float4*)b2)[c16 * 2];
        float4 bb  = ((const float4*)b2)[c16 * 2 + 1];

        float4 oa, ob;
        oa.x = dv * acc[0] + u2v * c1a.x + u1v * c2a.x + ba.x;
        oa.y = dv * acc[1] + u2v * c1a.y + u1v * c2a.y + ba.y;
        oa.z = dv * acc[2] + u2v * c1a.z + u1v * c2a.z + ba.z;
        oa.w = dv * acc[3] + u2v * c1a.w + u1v * c2a.w + ba.w;
        ob.x = dv * acc[4] + u2v * c1b.x + u1v * c2b.x + bb.x;
        ob.y = dv * acc[5] + u2v * c1b.y + u1v * c2b.y + bb.y;
        ob.z = dv * acc[6] + u2v * c1b.z + u1v * c2b.z + bb.z;
        ob.w = dv * acc[7] + u2v * c1b.w + u1v * c2b.w + bb.w;
        ((float4*)out)[(size_t)warp * 32 + c16 * 2]     = oa;
        ((float4*)out)[(size_t)warp * 32 + c16 * 2 + 1] = ob;
    }
}

// ---------------- launch: 3 streams ----------------
extern "C" void kernel_launch(void* const* d_in, const int* in_sizes, int n_in,
                              void* d_out, int out_size) {
    const float* feat = (const float*)d_in[0];
    const int*   ei   = (const int*)d_in[1];
    const float* W0 = (const float*)d_in[2];
    const float* b0 = (const float*)d_in[3];
    const float* W1 = (const float*)d_in[4];
    const float* b1 = (const float*)d_in[5];
    const float* W2 = (const float*)d_in[6];
    const float* b2 = (const float*)d_in[7];

    int n = in_sizes[0] / D;
    int e = in_sizes[1] / 2;
    if (n > NMAX) n = NMAX;
    if (e > EMAX) e = EMAX;
    const int* src = ei;
    const int* dstp = ei + e;

    __half *Hp, *Ap;
    float *Wtp, *W012p;
    cudaGetSymbolAddress((void**)&Hp, g_H);
    cudaGetSymbolAddress((void**)&Ap, g_A);
    cudaGetSymbolAddress((void**)&Wtp, g_Wt);
    cudaGetSymbolAddress((void**)&W012p, g_W012);

    static cudaStream_t sW = nullptr, sE = nullptr;
    static cudaEvent_t  eFork = nullptr, eW = nullptr, eDis = nullptr,
                        eCsr = nullptr, eScal = nullptr;
    if (!sW) {
        cudaStreamCreateWithFlags(&sW, cudaStreamNonBlocking);
        cudaStreamCreateWithFlags(&sE, cudaStreamNonBlocking);
        cudaEventCreateWithFlags(&eFork, cudaEventDisableTiming);
        cudaEventCreateWithFlags(&eW, cudaEventDisableTiming);
        cudaEventCreateWithFlags(&eDis, cudaEventDisableTiming);
        cudaEventCreateWithFlags(&eCsr, cudaEventDisableTiming);
        cudaEventCreateWithFlags(&eScal, cudaEventDisableTiming);
    }

    int nb = (n + 1023) / 1024;
    int gm = (n + 127) / 128;
    int ga = (int)(((long long)n * 32 + 255) / 256);
    int gn = (n + 255) / 256;
    int ge4 = (e + 1023) / 1024;

    cudaEventRecord(eFork, 0);

    // stream W: weight collapse (independent of graph)
    cudaStreamWaitEvent(sW, eFork, 0);
    k_mm128<<<64, 256, 0, sW>>>(W0, W1, Wtp);
    k_mm128<<<64, 256, 0, sW>>>(Wtp, W2, W012p);
    k_cvec<<<1, 128, 0, sW>>>(b0, b1, W1, W2);
    cudaEventRecord(eW, sW);

    // main: graph head (count -> fused scan incl. dis); cnt pre-zeroed by tail
    k_count<<<ge4, 256>>>(dstp, e);
    k_scan<<<nb, 1024>>>(n, e);
    cudaEventRecord(eDis, 0);

    // stream E: scatter + tail-zero + scalar aggs (need scan results)
    cudaStreamWaitEvent(sE, eDis, 0);
    k_scatter<<<ge4, 256, 0, sE>>>(src, dstp, e);
    cudaEventRecord(eCsr, sE);
    k_ztail<<<gn, 256, 0, sE>>>(n);          // reset cnt/sflag for next replay
    k_aggs1<<<gn, 256, 0, sE>>>(n);
    k_aggs2<<<gn, 256, 0, sE>>>(n);
    cudaEventRecord(eScal, sE);

    // main: gemm (needs dis from scan, W012 from sW)
    cudaStreamWaitEvent(0, eW, 0);
    k_gemm<<<gm, 256>>>(feat, W012p, Hp, n);

    // aggregations: mids need CSR + G0; fin additionally needs u1/u2
    cudaStreamWaitEvent(0, eCsr, 0);
    k_agg_mid<<<ga, 256>>>(Hp, Ap, n);
    k_agg_mid<<<ga, 256>>>(Ap, Hp, n);
    cudaStreamWaitEvent(0, eScal, 0);
    k_agg_fin<<<ga, 256>>>(Hp, b2, (float*)d_out, n);
}